// round 2
// baseline (speedup 1.0000x reference)
#include <cuda_runtime.h>
#include <cuda_bf16.h>

// TALayer = 9-tap 1D conv, tap offsets d_j = 16*(j/3) + (j%3) - 17
//   => groups g=0,1,2 start at dg = {-17, -1, +15}, 3 consecutive taps each.
// out[b,o,t] = bias[o] + sum_c sum_j W[o,c,j] * x[b,c,t+d_j]
//
// Round-2: packed fp32 math via fma.rn.f32x2 (FFMA2) to halve FFMA issue count.

#define NC 64
#define NO 64
#define KT 9
#define T_TILE 128
#define HALO 17
#define XT (T_TILE + 2 * HALO)   // 162
#define XSTRIDE XT

// Duplicated-pair transposed weights: g_wt2[((c*9 + j)*64 + o)*2 + {0,1}] = W[o,c,j]
__device__ float g_wt2[NC * KT * NO * 2];

__global__ void transpose_w_kernel(const float* __restrict__ w) {
    int i = blockIdx.x * blockDim.x + threadIdx.x;
    if (i < NO * NC * KT) {
        int o  = i / (NC * KT);
        int cj = i % (NC * KT);
        float v = w[i];
        g_wt2[(cj * NO + o) * 2 + 0] = v;
        g_wt2[(cj * NO + o) * 2 + 1] = v;
    }
}

__device__ __forceinline__ unsigned long long pack2(float lo, float hi) {
    unsigned long long r;
    asm("mov.b64 %0, {%1, %2};" : "=l"(r) : "f"(lo), "f"(hi));
    return r;
}

__device__ __forceinline__ void unpack2(unsigned long long v, float& lo, float& hi) {
    asm("mov.b64 {%0, %1}, %2;" : "=f"(lo), "=f"(hi) : "l"(v));
}

__device__ __forceinline__ void ffma2(unsigned long long& d,
                                      unsigned long long a,
                                      unsigned long long b) {
    asm("fma.rn.f32x2 %0, %1, %2, %0;" : "+l"(d) : "l"(a), "l"(b));
}

extern __shared__ float xs[];  // [NC][XSTRIDE]

__global__ __launch_bounds__(256, 3) void taconv_kernel(
    const float* __restrict__ x, const float* __restrict__ bias,
    float* __restrict__ out, int T)
{
    const int b    = blockIdx.y;
    const int base = blockIdx.x * T_TILE;
    const int tid  = threadIdx.x;
    const int lane = tid & 31;
    const int og   = tid >> 5;   // warp id = output-channel group (8 ch each)

    // ---- cooperative load of x tile (64 channels, T_TILE + 2*HALO) ----
    const float* xb = x + ((size_t)b * NC) * T;
    for (int c = 0; c < NC; ++c) {
        const float* xr = xb + (size_t)c * T;
        float* sr = xs + c * XSTRIDE;
        for (int i = tid; i < XT; i += 256) {
            int g = base - HALO + i;
            sr[i] = (g >= 0 && g < T) ? __ldg(xr + g) : 0.0f;
        }
    }
    __syncthreads();

    // ---- register tile: 8 output channels x 2 t-pairs (t = 2*lane + 64*k) ----
    unsigned long long acc[16];
#pragma unroll
    for (int i = 0; i < 16; ++i) acc[i] = 0ULL;

    for (int c = 0; c < NC; ++c) {
        const float* xr = xs + c * XSTRIDE + HALO + 2 * lane;
        const float* wc = g_wt2 + (size_t)(c * KT) * (NO * 2) + og * 16;

#pragma unroll
        for (int g = 0; g < 3; ++g) {
            const int dg = 16 * g - 17;      // -17, -1, +15

            // x windows: for pair base e = 2*lane + 64k + dg, need x[e..e+3]
            unsigned long long p[3][2];
#pragma unroll
            for (int k = 0; k < 2; ++k) {
                const float* xp = xr + dg + 64 * k;
                float a0 = xp[0], a1 = xp[1], a2 = xp[2], a3 = xp[3];
                p[0][k] = pack2(a0, a1);
                p[1][k] = pack2(a1, a2);
                p[2][k] = pack2(a2, a3);
            }

#pragma unroll
            for (int jj = 0; jj < 3; ++jj) {
                const int j = 3 * g + jj;
                // 8 duplicated weight pairs = 16 floats = 4x LDG.128
                const float4* wj = (const float4*)(wc + j * (NO * 2));
                float4 w0 = __ldg(wj + 0);
                float4 w1 = __ldg(wj + 1);
                float4 w2 = __ldg(wj + 2);
                float4 w3 = __ldg(wj + 3);
                unsigned long long wp[8];
                wp[0] = pack2(w0.x, w0.y); wp[1] = pack2(w0.z, w0.w);
                wp[2] = pack2(w1.x, w1.y); wp[3] = pack2(w1.z, w1.w);
                wp[4] = pack2(w2.x, w2.y); wp[5] = pack2(w2.z, w2.w);
                wp[6] = pack2(w3.x, w3.y); wp[7] = pack2(w3.z, w3.w);
#pragma unroll
                for (int o = 0; o < 8; ++o) {
#pragma unroll
                    for (int k = 0; k < 2; ++k)
                        ffma2(acc[o * 2 + k], wp[o], p[jj][k]);
                }
            }
        }
    }

    // ---- epilogue: add bias, coalesced float2 stores ----
    float* ob = out + ((size_t)b * NO + og * 8) * T + base + 2 * lane;
#pragma unroll
    for (int o = 0; o < 8; ++o) {
        float bv = __ldg(bias + og * 8 + o);
        float* op = ob + (size_t)o * T;
#pragma unroll
        for (int k = 0; k < 2; ++k) {
            float lo, hi;
            unpack2(acc[o * 2 + k], lo, hi);
            ((float2*)(op + 64 * k))[0] = make_float2(lo + bv, hi + bv);
        }
    }
}

extern "C" void kernel_launch(void* const* d_in, const int* in_sizes, int n_in,
                              void* d_out, int out_size) {
    const float* x    = (const float*)d_in[0];
    const float* w    = (const float*)d_in[1];
    const float* bias = (const float*)d_in[2];
    float* out = (float*)d_out;

    const int T = 65536;
    const int B = in_sizes[0] / (NC * T);

    transpose_w_kernel<<<(NO * NC * KT + 255) / 256, 256>>>(w);

    size_t smem = (size_t)NC * XSTRIDE * sizeof(float);   // 41,472 B
    cudaFuncSetAttribute(taconv_kernel,
                         cudaFuncAttributeMaxDynamicSharedMemorySize, (int)smem);

    dim3 grid((T + T_TILE - 1) / T_TILE, B);
    taconv_kernel<<<grid, 256, smem>>>(x, bias, out, T);
}

// round 4
// speedup vs baseline: 2.3190x; 2.3190x over previous
#include <cuda_runtime.h>
#include <cstdint>

// TALayer = 9-tap conv, tap offsets d_j = 16*(j/3)+(j%3)-17.
// GEMM form: D[o,t] = sum_k W[o,k]*X[k,t], k=(j,c), K=576,
//   X[(j,c), t] = x[c][t + d_j]  (zero-padded).
// Warp-level mma.sync m16n8k8 TF32 (HMMA), fragments hand-staged in smem.

#define T_LEN  65536
#define NO     64
#define NC     64
#define T_TILE 256
#define HALO   17
#define XROWS  (T_TILE + 2*HALO)   // 290
#define XSTR   68                  // words per x row (64 + 4 pad)
#define NCHUNK 72                  // K=576 / 8
#define GRID   148
#define NTILES 2048                // 8 * 65536/256

// smem byte offsets
#define WFOFF   0
#define WFBYTES (NCHUNK*4*32*16)        // 147456: [chunk][mtile][lane]{a0..a3}
#define XSOFF   WFBYTES
#define XSBYTES (XROWS*XSTR*4)          // 78880
#define BOFF    (XSOFF + XSBYTES)       // 226336
#define SMTOT   (BOFF + 256)            // 226592

// Prep scratch: W fragments in tf32, exact mma A-fragment register layout.
__device__ float g_wfrag[NCHUNK*4*32*4];

__device__ __forceinline__ uint32_t f2tf32(float f) {
    uint32_t u;
    asm("cvt.rna.tf32.f32 %0, %1;" : "=r"(u) : "f"(f));
    return u;
}

__global__ void prep_w(const float* __restrict__ w) {
    int tid = blockIdx.x * blockDim.x + threadIdx.x;
    if (tid >= NCHUNK * 128) return;
    int q = tid >> 7, r = tid & 127, mt = r >> 5, lane = r & 31;
    int j = q >> 3, cq = q & 7;
    int o0 = mt * 16 + (lane >> 2);
    int c0 = cq * 8 + (lane & 3);
    uint4 u;
    u.x = f2tf32(w[o0 * 576 + c0 * 9 + j]);        // a0: (o0,     c0)
    u.y = f2tf32(w[(o0 + 8) * 576 + c0 * 9 + j]);  // a1: (o0+8,   c0)
    u.z = f2tf32(w[o0 * 576 + (c0 + 4) * 9 + j]);  // a2: (o0,     c0+4)
    u.w = f2tf32(w[(o0 + 8) * 576 + (c0 + 4) * 9 + j]);
    ((uint4*)g_wfrag)[tid] = u;
}

extern __shared__ char sm[];

__global__ __launch_bounds__(256, 1) void taconv_mma(
    const float* __restrict__ x, const float* __restrict__ bias,
    float* __restrict__ out)
{
    const int tid  = threadIdx.x;
    const int wid  = tid >> 5;
    const int lane = tid & 31;

    // ---- stage W fragments + bias into smem (once) ----
    {
        const float4* gw = (const float4*)g_wfrag;
        float4* sw = (float4*)(sm + WFOFF);
        for (int i = tid; i < WFBYTES / 16; i += 256) sw[i] = gw[i];
        if (tid < 64) ((float*)(sm + BOFF))[tid] = bias[tid];
    }

    const int wrow = wid * 32 + (lane >> 2);   // B-frag t-row base (pre-shift)

    for (int tile = blockIdx.x; tile < NTILES; tile += GRID) {
        const int b  = tile >> 8;
        const int t0 = (tile & 255) << 8;

        __syncthreads();   // xs safe to overwrite; also covers W staging (iter 0)

        // ---- x tile -> smem, t-major: xs[i][c], i = t - t0 + HALO ----
        const float* xb = x + (size_t)b * NC * T_LEN;
        float* xs = (float*)(sm + XSOFF);
        for (int it = 0; it < 73; ++it) {
            int idx = it * 256 + tid;              // idx = c*290 + i
            if (idx < NC * XROWS) {
                int c = idx / XROWS, i = idx - c * XROWS;
                int g = t0 - HALO + i;
                float v = (g >= 0 && g < T_LEN)
                        ? __ldg(xb + (size_t)c * T_LEN + g) : 0.0f;
                xs[i * XSTR + c] = v;
            }
        }
        __syncthreads();

        // ---- mainloop: 72 K-chunks, 16 mma each ----
        float acc[4][4][4];
#pragma unroll
        for (int m = 0; m < 4; ++m)
#pragma unroll
            for (int n = 0; n < 4; ++n)
#pragma unroll
                for (int r = 0; r < 4; ++r) acc[m][n][r] = 0.0f;

        const uint32_t* xw = (const uint32_t*)(sm + XSOFF);
        const uint4*    wf_base = (const uint4*)(sm + WFOFF);

#pragma unroll
        for (int j = 0; j < 9; ++j) {
            const int offj = 16 * (j / 3) + (j % 3);   // d_j + HALO
#pragma unroll
            for (int cq = 0; cq < 8; ++cq) {
                const int q = j * 8 + cq;
                uint4 wf[4];
#pragma unroll
                for (int mt = 0; mt < 4; ++mt)
                    wf[mt] = wf_base[(q * 4 + mt) * 32 + lane];

                uint32_t bb[4][2];
                const uint32_t* bp =
                    xw + (wrow + offj) * XSTR + cq * 8 + (lane & 3);
#pragma unroll
                for (int nt = 0; nt < 4; ++nt) {
                    bb[nt][0] = f2tf32(__uint_as_float(bp[nt * 8 * XSTR]));
                    bb[nt][1] = f2tf32(__uint_as_float(bp[nt * 8 * XSTR + 4]));
                }
#pragma unroll
                for (int mt = 0; mt < 4; ++mt)
#pragma unroll
                    for (int nt = 0; nt < 4; ++nt)
                        asm volatile(
                            "mma.sync.aligned.m16n8k8.row.col.f32.tf32.tf32.f32 "
                            "{%0,%1,%2,%3}, {%4,%5,%6,%7}, {%8,%9}, {%0,%1,%2,%3};"
                            : "+f"(acc[mt][nt][0]), "+f"(acc[mt][nt][1]),
                              "+f"(acc[mt][nt][2]), "+f"(acc[mt][nt][3])
                            : "r"(wf[mt].x), "r"(wf[mt].y),
                              "r"(wf[mt].z), "r"(wf[mt].w),
                              "r"(bb[nt][0]), "r"(bb[nt][1]));
            }
        }

        // ---- epilogue: +bias, STG.64 per C-fragment pair ----
        float* ob = out + (size_t)b * NO * T_LEN + t0 + wid * 32 + 2 * (lane & 3);
#pragma unroll
        for (int mt = 0; mt < 4; ++mt) {
            int oA = mt * 16 + (lane >> 2);
            float bv0 = ((float*)(sm + BOFF))[oA];
            float bv1 = ((float*)(sm + BOFF))[oA + 8];
#pragma unroll
            for (int nt = 0; nt < 4; ++nt) {
                float2 v0 = make_float2(acc[mt][nt][0] + bv0,
                                        acc[mt][nt][1] + bv0);
                float2 v1 = make_float2(acc[mt][nt][2] + bv1,
                                        acc[mt][nt][3] + bv1);
                *(float2*)(ob + (size_t)oA * T_LEN + nt * 8) = v0;
                *(float2*)(ob + (size_t)(oA + 8) * T_LEN + nt * 8) = v1;
            }
        }
    }
}

extern "C" void kernel_launch(void* const* d_in, const int* in_sizes, int n_in,
                              void* d_out, int out_size) {
    const float* x    = (const float*)d_in[0];
    const float* w    = (const float*)d_in[1];
    const float* bias = (const float*)d_in[2];
    float* out = (float*)d_out;

    prep_w<<<(NCHUNK * 128 + 255) / 256, 256>>>(w);

    cudaFuncSetAttribute(taconv_mma,
                         cudaFuncAttributeMaxDynamicSharedMemorySize, SMTOT);
    taconv_mma<<<GRID, 256, SMTOT>>>(x, bias, out);
}

// round 5
// speedup vs baseline: 3.5249x; 1.5200x over previous
#include <cuda_runtime.h>
#include <cstdint>

// TALayer = 9-tap conv, tap offsets d_j = 16*(j/3)+(j%3)-17.
// GEMM form: D[o,t] = sum_k W[o,k]*X[k,t], k=(j,c), K=576.
// Warp-level mma.sync m16n8k8 TF32; 512-thread CTA (16 warps), warp=32o x 32t.

#define T_LEN  65536
#define NO     64
#define NC     64
#define T_TILE 256
#define HALO   17
#define XROWS  (T_TILE + 2*HALO)   // 290
#define XSTR   68                  // words per x row (64 + 4 pad)
#define NCHUNK 72                  // K=576 / 8
#define GRID   148
#define NTILES 2048                // 8 * 65536/256

// smem byte offsets
#define WFOFF   0
#define WFBYTES (NCHUNK*4*32*16)        // 147456: [chunk][mtile][lane]{a0..a3}
#define XSOFF   WFBYTES
#define XSBYTES (XROWS*XSTR*4)          // 78880
#define BOFF    (XSOFF + XSBYTES)       // 226336
#define SMTOT   (BOFF + 256)            // 226592

__device__ float g_wfrag[NCHUNK*4*32*4];

__device__ __forceinline__ uint32_t f2tf32(float f) {
    uint32_t u;
    asm("cvt.rna.tf32.f32 %0, %1;" : "=r"(u) : "f"(f));
    return u;
}

__global__ void prep_w(const float* __restrict__ w) {
    int tid = blockIdx.x * blockDim.x + threadIdx.x;
    if (tid >= NCHUNK * 128) return;
    int q = tid >> 7, r = tid & 127, mt = r >> 5, lane = r & 31;
    int j = q >> 3, cq = q & 7;
    int o0 = mt * 16 + (lane >> 2);
    int c0 = cq * 8 + (lane & 3);
    uint4 u;
    u.x = f2tf32(w[o0 * 576 + c0 * 9 + j]);        // a0: (o0,   c0)
    u.y = f2tf32(w[(o0 + 8) * 576 + c0 * 9 + j]);  // a1: (o0+8, c0)
    u.z = f2tf32(w[o0 * 576 + (c0 + 4) * 9 + j]);  // a2: (o0,   c0+4)
    u.w = f2tf32(w[(o0 + 8) * 576 + (c0 + 4) * 9 + j]);
    ((uint4*)g_wfrag)[tid] = u;
}

extern __shared__ char sm[];

__global__ __launch_bounds__(512, 1) void taconv_mma(
    const float* __restrict__ x, const float* __restrict__ bias,
    float* __restrict__ out)
{
    const int tid  = threadIdx.x;
    const int wid  = tid >> 5;
    const int lane = tid & 31;
    const int og   = wid & 1;        // o-half: 32 output channels
    const int tg   = wid >> 1;       // t-group: 32 time steps

    // ---- stage W fragments + bias into smem (once) ----
    {
        const float4* gw = (const float4*)g_wfrag;
        float4* sw = (float4*)(sm + WFOFF);
        for (int i = tid; i < WFBYTES / 16; i += 512) sw[i] = gw[i];
        if (tid < 64) ((float*)(sm + BOFF))[tid] = bias[tid];
    }

    const int wrow = tg * 32 + (lane >> 2);   // B-frag t-row base (pre-shift)

    for (int tile = blockIdx.x; tile < NTILES; tile += GRID) {
        const int b  = tile >> 8;
        const int t0 = (tile & 255) << 8;

        __syncthreads();   // xs safe to overwrite; covers W staging on iter 0

        // ---- x tile -> smem as TF32 bits, t-major: xs[i][c] ----
        const float* xb = x + (size_t)b * NC * T_LEN;
        uint32_t* xs = (uint32_t*)(sm + XSOFF);
        for (int it = 0; it < 37; ++it) {
            int idx = it * 512 + tid;              // idx = c*290 + i
            if (idx < NC * XROWS) {
                int c = idx / XROWS, i = idx - c * XROWS;
                int g = t0 - HALO + i;
                float v = (g >= 0 && g < T_LEN)
                        ? __ldg(xb + (size_t)c * T_LEN + g) : 0.0f;
                xs[i * XSTR + c] = f2tf32(v);
            }
        }
        __syncthreads();

        // ---- mainloop: 72 K-chunks, 8 mma each ----
        float acc[2][4][4];
#pragma unroll
        for (int m = 0; m < 2; ++m)
#pragma unroll
            for (int n = 0; n < 4; ++n)
#pragma unroll
                for (int r = 0; r < 4; ++r) acc[m][n][r] = 0.0f;

        const uint4* wf_base = (const uint4*)(sm + WFOFF);

#pragma unroll
        for (int j = 0; j < 9; ++j) {
            const int offj = 16 * (j / 3) + (j % 3);   // d_j + HALO
#pragma unroll
            for (int cq = 0; cq < 8; ++cq) {
                const int q = j * 8 + cq;
                uint4 wf[2];
#pragma unroll
                for (int m = 0; m < 2; ++m)
                    wf[m] = wf_base[(q * 4 + og * 2 + m) * 32 + lane];

                uint32_t bb[4][2];
                const uint32_t* bp =
                    xs + (wrow + offj) * XSTR + cq * 8 + (lane & 3);
#pragma unroll
                for (int nt = 0; nt < 4; ++nt) {
                    bb[nt][0] = bp[nt * 8 * XSTR];
                    bb[nt][1] = bp[nt * 8 * XSTR + 4];
                }
#pragma unroll
                for (int m = 0; m < 2; ++m)
#pragma unroll
                    for (int nt = 0; nt < 4; ++nt)
                        asm volatile(
                            "mma.sync.aligned.m16n8k8.row.col.f32.tf32.tf32.f32 "
                            "{%0,%1,%2,%3}, {%4,%5,%6,%7}, {%8,%9}, {%0,%1,%2,%3};"
                            : "+f"(acc[m][nt][0]), "+f"(acc[m][nt][1]),
                              "+f"(acc[m][nt][2]), "+f"(acc[m][nt][3])
                            : "r"(wf[m].x), "r"(wf[m].y),
                              "r"(wf[m].z), "r"(wf[m].w),
                              "r"(bb[nt][0]), "r"(bb[nt][1]));
            }
        }

        // ---- epilogue: +bias, STG.64 per C-fragment pair ----
        float* ob = out + (size_t)b * NO * T_LEN + t0 + tg * 32 + 2 * (lane & 3);
#pragma unroll
        for (int m = 0; m < 2; ++m) {
            int oA = og * 32 + m * 16 + (lane >> 2);
            float bv0 = ((float*)(sm + BOFF))[oA];
            float bv1 = ((float*)(sm + BOFF))[oA + 8];
#pragma unroll
            for (int nt = 0; nt < 4; ++nt) {
                float2 v0 = make_float2(acc[m][nt][0] + bv0,
                                        acc[m][nt][1] + bv0);
                float2 v1 = make_float2(acc[m][nt][2] + bv1,
                                        acc[m][nt][3] + bv1);
                *(float2*)(ob + (size_t)oA * T_LEN + nt * 8) = v0;
                *(float2*)(ob + (size_t)(oA + 8) * T_LEN + nt * 8) = v1;
            }
        }
    }
}

extern "C" void kernel_launch(void* const* d_in, const int* in_sizes, int n_in,
                              void* d_out, int out_size) {
    const float* x    = (const float*)d_in[0];
    const float* w    = (const float*)d_in[1];
    const float* bias = (const float*)d_in[2];
    float* out = (float*)d_out;

    prep_w<<<(NCHUNK * 128 + 255) / 256, 256>>>(w);

    cudaFuncSetAttribute(taconv_mma,
                         cudaFuncAttributeMaxDynamicSharedMemorySize, SMTOT);
    taconv_mma<<<GRID, 512, SMTOT>>>(x, bias, out);
}

// round 6
// speedup vs baseline: 6.5001x; 1.8441x over previous
#include <cuda_runtime.h>
#include <cuda_fp16.h>
#include <cstdint>

// TALayer = 9-tap conv, tap offsets d_j = 16*(j/3)+(j%3)-17.
// GEMM form: D[o,t] = sum_k W[o,k]*X[k,t], k=(j,c), K=576.
// fp16 mma.sync m16n8k16 (fp32 accum). 2 CTAs/SM x 256 thr, warp = 32o x 32t.

#define T_LEN  65536
#define NO     64
#define NC     64
#define T_TILE 128
#define HALO   17
#define XROWS  (T_TILE + 2*HALO)   // 162
#define XSTW   36                  // words (uint32) per x row: 32 data + 4 pad
#define NCHUNK 36                  // K=576 / 16
#define GRID   296                 // 2 CTAs/SM * 148
#define NTILES 4096                // 8 * 65536/128

// smem byte offsets
#define WFOFF   0
#define WFBYTES (NCHUNK*4*32*16)        // 73728: [chunk][mtile][lane]{a0..a3}
#define XSOFF   WFBYTES
#define XSBYTES (XROWS*XSTW*4)          // 23328
#define BOFF    (XSOFF + XSBYTES)       // 97056
#define SMTOT   (BOFF + 256)            // 97312

// W fragments in exact m16n8k16 f16 A-fragment layout (packed half2 per reg).
__device__ uint32_t g_wfrag[NCHUNK*4*32*4];

__device__ __forceinline__ uint32_t packh2(float lo, float hi) {
    __half2 h = __floats2half2_rn(lo, hi);
    return *(uint32_t*)&h;
}

__global__ void prep_w(const float* __restrict__ w) {
    int tid = blockIdx.x * blockDim.x + threadIdx.x;
    if (tid >= NCHUNK * 128) return;
    int q = tid >> 7, r = tid & 127, mt = r >> 5, lane = r & 31;
    int j = q >> 2, cq = q & 3;            // chunk = (tap j, c-block of 16)
    int o0 = mt * 16 + (lane >> 2);
    int c0 = cq * 16 + (lane & 3) * 2;
    uint4 u;
    u.x = packh2(w[o0*576 + c0*9 + j],       w[o0*576 + (c0+1)*9 + j]);
    u.y = packh2(w[(o0+8)*576 + c0*9 + j],   w[(o0+8)*576 + (c0+1)*9 + j]);
    u.z = packh2(w[o0*576 + (c0+8)*9 + j],   w[o0*576 + (c0+9)*9 + j]);
    u.w = packh2(w[(o0+8)*576 + (c0+8)*9+j], w[(o0+8)*576 + (c0+9)*9 + j]);
    ((uint4*)g_wfrag)[tid] = u;
}

extern __shared__ char sm[];

__global__ __launch_bounds__(256, 2) void taconv_mma(
    const float* __restrict__ x, const float* __restrict__ bias,
    float* __restrict__ out)
{
    const int tid  = threadIdx.x;
    const int wid  = tid >> 5;
    const int lane = tid & 31;
    const int og   = wid & 1;        // o-half: 32 output channels
    const int tg   = wid >> 1;       // t-group: 32 time steps

    // ---- stage W fragments + bias into smem (once) ----
    {
        const uint4* gw = (const uint4*)g_wfrag;
        uint4* sw = (uint4*)(sm + WFOFF);
        for (int i = tid; i < WFBYTES / 16; i += 256) sw[i] = gw[i];
        if (tid < 64) ((float*)(sm + BOFF))[tid] = bias[tid];
    }

    const int wrow = tg * 32 + (lane >> 2);   // B-frag t-row base (pre-shift)

    for (int tile = blockIdx.x; tile < NTILES; tile += GRID) {
        const int b  = tile >> 9;
        const int t0 = (tile & 511) << 7;

        __syncthreads();   // xs safe to overwrite; covers W staging on iter 0

        // ---- x tile -> smem as fp16, t-major: xs[i][c] (c pairs per word) ----
        const float* xb = x + (size_t)b * NC * T_LEN;
        __half* xsh = (__half*)(sm + XSOFF);
#pragma unroll 6
        for (int it = 0; it < 41; ++it) {
            int idx = it * 256 + tid;              // idx = c*162 + i
            if (idx < NC * XROWS) {
                int c = idx / XROWS, i = idx - c * XROWS;
                int g = t0 - HALO + i;
                float v = (g >= 0 && g < T_LEN)
                        ? __ldg(xb + (size_t)c * T_LEN + g) : 0.0f;
                xsh[i * (2 * XSTW) + c] = __float2half_rn(v);
            }
        }
        __syncthreads();

        // ---- mainloop: 36 K-chunks (k=16), 8 mma each ----
        float acc[2][4][4];
#pragma unroll
        for (int m = 0; m < 2; ++m)
#pragma unroll
            for (int n = 0; n < 4; ++n)
#pragma unroll
                for (int r = 0; r < 4; ++r) acc[m][n][r] = 0.0f;

        const uint4* wf_base = (const uint4*)(sm + WFOFF);
        const uint32_t* xs = (const uint32_t*)(sm + XSOFF);

#pragma unroll
        for (int j = 0; j < 9; ++j) {
            const int offj = 16 * (j / 3) + (j % 3);   // d_j + HALO
#pragma unroll
            for (int cq = 0; cq < 4; ++cq) {
                const int q = j * 4 + cq;
                uint4 wf[2];
#pragma unroll
                for (int m = 0; m < 2; ++m)
                    wf[m] = wf_base[(q * 4 + og * 2 + m) * 32 + lane];

                uint32_t bb[4][2];
                const uint32_t* bp =
                    xs + (wrow + offj) * XSTW + cq * 8 + (lane & 3);
#pragma unroll
                for (int nt = 0; nt < 4; ++nt) {
                    bb[nt][0] = bp[nt * 8 * XSTW];
                    bb[nt][1] = bp[nt * 8 * XSTW + 4];
                }
#pragma unroll
                for (int m = 0; m < 2; ++m)
#pragma unroll
                    for (int nt = 0; nt < 4; ++nt)
                        asm volatile(
                            "mma.sync.aligned.m16n8k16.row.col.f32.f16.f16.f32 "
                            "{%0,%1,%2,%3}, {%4,%5,%6,%7}, {%8,%9}, {%0,%1,%2,%3};"
                            : "+f"(acc[m][nt][0]), "+f"(acc[m][nt][1]),
                              "+f"(acc[m][nt][2]), "+f"(acc[m][nt][3])
                            : "r"(wf[m].x), "r"(wf[m].y),
                              "r"(wf[m].z), "r"(wf[m].w),
                              "r"(bb[nt][0]), "r"(bb[nt][1]));
            }
        }

        // ---- epilogue: +bias, STG.64 per C-fragment pair ----
        float* ob = out + (size_t)b * NO * T_LEN + t0 + tg * 32 + 2 * (lane & 3);
#pragma unroll
        for (int m = 0; m < 2; ++m) {
            int oA = og * 32 + m * 16 + (lane >> 2);
            float bv0 = ((float*)(sm + BOFF))[oA];
            float bv1 = ((float*)(sm + BOFF))[oA + 8];
#pragma unroll
            for (int nt = 0; nt < 4; ++nt) {
                float2 v0 = make_float2(acc[m][nt][0] + bv0,
                                        acc[m][nt][1] + bv0);
                float2 v1 = make_float2(acc[m][nt][2] + bv1,
                                        acc[m][nt][3] + bv1);
                *(float2*)(ob + (size_t)oA * T_LEN + nt * 8) = v0;
                *(float2*)(ob + (size_t)(oA + 8) * T_LEN + nt * 8) = v1;
            }
        }
    }
}

extern "C" void kernel_launch(void* const* d_in, const int* in_sizes, int n_in,
                              void* d_out, int out_size) {
    const float* x    = (const float*)d_in[0];
    const float* w    = (const float*)d_in[1];
    const float* bias = (const float*)d_in[2];
    float* out = (float*)d_out;

    prep_w<<<(NCHUNK * 128 + 255) / 256, 256>>>(w);

    cudaFuncSetAttribute(taconv_mma,
                         cudaFuncAttributeMaxDynamicSharedMemorySize, SMTOT);
    taconv_mma<<<GRID, 256, SMTOT>>>(x, bias, out);
}